// round 6
// baseline (speedup 1.0000x reference)
#include <cuda_runtime.h>
#include <cstdint>

#define BSZ 8
#define CIN 256
#define COUT 256
#define HH 64
#define WW 64
#define KK (CIN * 9)          // 2304
#define NTOT (BSZ * HH * WW)  // 32768

#define BM 128
#define BN 256
#define BK 16
#define NITER (KK / BK)       // 144
#define THREADS 512
#define NSTAGE 4

// Scratch
__device__ float g_xm[BSZ * CIN * HH * WW];   // style-modulated, tf32-rounded input
__device__ float g_wt[COUT * KK];             // tap-major tf32 weights: [co][tap][ci]
__device__ float g_wsq[COUT * CIN];
__device__ float g_rsigma[BSZ * COUT];

// ---------------------------------------------------------------------------
__device__ __forceinline__ uint32_t smem_u32(const void* p) {
    uint32_t a;
    asm("{ .reg .u64 t; cvta.to.shared.u64 t, %1; cvt.u32.u64 %0, t; }" : "=r"(a) : "l"(p));
    return a;
}
__device__ __forceinline__ float to_tf32(float f) {
    uint32_t u;
    asm("cvt.rna.tf32.f32 %0, %1;" : "=r"(u) : "f"(f));
    return __uint_as_float(u);
}
__device__ __forceinline__ void ldsm_x4(uint32_t* r, uint32_t addr) {
    asm volatile("ldmatrix.sync.aligned.m8n8.x4.shared.b16 {%0,%1,%2,%3}, [%4];"
                 : "=r"(r[0]), "=r"(r[1]), "=r"(r[2]), "=r"(r[3]) : "r"(addr));
}
__device__ __forceinline__ void mma_tf32(float* d, const uint32_t* a, uint32_t b0, uint32_t b1) {
    asm volatile(
        "mma.sync.aligned.m16n8k8.row.col.f32.tf32.tf32.f32 "
        "{%0,%1,%2,%3}, {%4,%5,%6,%7}, {%8,%9}, {%0,%1,%2,%3};"
        : "+f"(d[0]), "+f"(d[1]), "+f"(d[2]), "+f"(d[3])
        : "r"(a[0]), "r"(a[1]), "r"(a[2]), "r"(a[3]), "r"(b0), "r"(b1));
}
__device__ __forceinline__ void cp_async4(uint32_t dst, const void* src, uint32_t sz) {
    asm volatile("cp.async.ca.shared.global [%0], [%1], 4, %2;"
                 :: "r"(dst), "l"(src), "r"(sz) : "memory");
}
__device__ __forceinline__ void cp_async16(uint32_t dst, const void* src) {
    asm volatile("cp.async.cg.shared.global [%0], [%1], 16;"
                 :: "r"(dst), "l"(src) : "memory");
}
#define CP_COMMIT() asm volatile("cp.async.commit_group;" ::: "memory")
#define CP_WAIT(n)  asm volatile("cp.async.wait_group %0;" :: "n"(n) : "memory")

// ---------------------------------------------------------------------------
// Pre-kernels
// ---------------------------------------------------------------------------
__global__ void wsq_kernel(const float* __restrict__ w) {
    int idx = blockIdx.x * blockDim.x + threadIdx.x;
    if (idx >= COUT * CIN) return;
    const float* p = w + idx * 9;
    float s = 0.f;
#pragma unroll
    for (int i = 0; i < 9; i++) s += p[i] * p[i];
    g_wsq[idx] = s;
}

__global__ void sigma_kernel(const float* __restrict__ style) {
    __shared__ float s2[CIN];
    int b = blockIdx.x;
    for (int i = threadIdx.x; i < CIN; i += blockDim.x) {
        float s = style[b * CIN + i];
        s2[i] = s * s;
    }
    __syncthreads();
    int co = threadIdx.x;
    const float* wr = g_wsq + co * CIN;
    float acc = 0.f;
#pragma unroll 4
    for (int ci = 0; ci < CIN; ci++) acc += s2[ci] * wr[ci];
    g_rsigma[b * COUT + co] = rsqrtf(acc + 1e-8f);
}

// tap-major transpose + tf32 round: g_wt[co][tap][ci] = rna(w[co][ci][tap])
__global__ void wt_kernel(const float* __restrict__ w) {
    int idx = blockIdx.x * blockDim.x + threadIdx.x;
    if (idx >= COUT * KK) return;
    int co = idx / KK;
    int r = idx - co * KK;
    int tap = r >> 8;
    int ci = r & 255;
    g_wt[idx] = to_tf32(w[co * KK + ci * 9 + tap]);
}

__global__ void modx_kernel(const float* __restrict__ x, const float* __restrict__ style) {
    int idx = blockIdx.x * blockDim.x + threadIdx.x;
    const int n4 = BSZ * CIN * HH * WW / 4;
    if (idx >= n4) return;
    int plane = idx / (HH * WW / 4);
    float s = style[plane];
    float4 v = ((const float4*)x)[idx];
    v.x = to_tf32(v.x * s);
    v.y = to_tf32(v.y * s);
    v.z = to_tf32(v.z * s);
    v.w = to_tf32(v.w * s);
    ((float4*)g_xm)[idx] = v;
}

// ---------------------------------------------------------------------------
// tf32 mma.sync implicit-GEMM conv: tap-major K, cp.async 4-stage pipeline,
// 512 threads, 16 warps of 32(M)x64(N), ONE barrier per iteration.
// ---------------------------------------------------------------------------
#define ROWF 20                       // floats per smem row (16 + 4 pad)
#define SA_B (BM * ROWF * 4)          // 10240 B
#define SB_B (BN * ROWF * 4)          // 20480 B
#define STG_B (SA_B + SB_B)           // 30720 B

__global__ __launch_bounds__(THREADS, 1)
void conv_mma(float* __restrict__ out) {
    extern __shared__ float sm[];
    const uint32_t smb = smem_u32(sm);

    const int tid = threadIdx.x;
    const int lane = tid & 31;
    const int warp = tid >> 5;

    const int m0c = blockIdx.y * BM;
    const int n0c = blockIdx.x * BN;
    const int b = n0c >> 12;
    const char* xb = (const char*)(g_xm + (size_t)b * CIN * 4096);

    // --- A loader: 128 rows x 16 floats; 512 threads -> one 16B each ---
    const int arow = tid >> 2;
    const int aq   = (tid & 3) * 4;
    const float* wa_base = g_wt + (size_t)(m0c + arow) * KK + aq;
    const uint32_t a_dst0 = (uint32_t)((arow * ROWF + aq) * 4);

    // --- B loader: 256 rows x 16 k; 2 threads/row, 8 k each (4B cp.async) ---
    const int bn = tid >> 1;
    const int bh = (tid & 1) * 8;
    const int nn = n0c + bn;
    const int wc = nn & 63;
    const int hr = (nn >> 6) & 63;
    const uint32_t b_dst0 = (uint32_t)(SA_B + (bn * ROWF + bh) * 4);

    // --- compute mapping: 16 warps, warp tile 32x64 (verified in R4) ---
    const int wm = (warp >> 2) * 32;      // 0,32,64,96
    const int wn = (warp & 3) * 64;       // 0,64,128,192
    const uint32_t a_byte = (uint32_t)(((wm + (lane & 15)) * ROWF + (lane >> 4) * 4) * 4);
    const uint32_t b_byte =
        (uint32_t)(((wn + (lane & 7) + ((lane >> 4) << 3)) * ROWF + ((lane >> 3) & 1) * 4) * 4);

    float acc[2][8][4];
#pragma unroll
    for (int i = 0; i < 2; i++)
#pragma unroll
        for (int j = 0; j < 8; j++)
#pragma unroll
            for (int q = 0; q < 4; q++) acc[i][j][q] = 0.f;

    // --- tap state for the load iterator ---
    int kh = 0, kw = 0;
    int hs = hr - 1, ws = wc - 1;
    uint32_t bsz = ((unsigned)hs < 64u && (unsigned)ws < 64u) ? 4u : 0u;
    uint32_t spb = bsz ? (uint32_t)((hs * 64 + ws) * 4) : 0u;

    auto issue_loads = [&](int lt, int stage) {
        const uint32_t sbase = smb + (uint32_t)(stage * STG_B);
        cp_async16(sbase + a_dst0, wa_base + lt * BK);
        const int ci0 = ((lt & 15) << 4) + bh;
        const char* bsrc = xb + (size_t)ci0 * 16384 + spb;
#pragma unroll
        for (int j = 0; j < 8; j++)
            cp_async4(sbase + b_dst0 + (uint32_t)(j * 4), bsrc + (size_t)j * 16384, bsz);
        CP_COMMIT();
    };
    auto advance_tap = [&]() {
        kw++;
        if (kw == 3) { kw = 0; kh++; }
        hs = hr + kh - 1;
        ws = wc + kw - 1;
        bsz = ((unsigned)hs < 64u && (unsigned)ws < 64u) ? 4u : 0u;
        spb = bsz ? (uint32_t)((hs * 64 + ws) * 4) : 0u;
    };

    // ---- prologue: issue iters 0..2 (all tap 0) ----
#pragma unroll
    for (int p = 0; p < NSTAGE - 1; p++) issue_loads(p, p);

    int stage = 0;
    for (int it = 0; it < NITER; it++) {
        CP_WAIT(NSTAGE - 2);
        __syncthreads();   // single barrier per iteration

        // issue loads for it + 3 into stage (stage+3)%4 — never a live read stage
        const int lt = it + NSTAGE - 1;
        if (lt < NITER) {
            if ((lt & 15) == 0) advance_tap();
            int wst = stage + (NSTAGE - 1);
            if (wst >= NSTAGE) wst -= NSTAGE;
            issue_loads(lt, wst);
        }

        // ---- compute on 'stage' ----
        const uint32_t sAs = smb + (uint32_t)(stage * STG_B);
        const uint32_t sBs = sAs + (uint32_t)SA_B;
#pragma unroll
        for (int ks = 0; ks < 2; ks++) {
            uint32_t afr[2][4], bfr[4][4];
#pragma unroll
            for (int mi = 0; mi < 2; mi++)
                ldsm_x4(afr[mi], sAs + a_byte + (uint32_t)(mi * 16 * ROWF * 4 + ks * 32));
#pragma unroll
            for (int nj = 0; nj < 4; nj++)
                ldsm_x4(bfr[nj], sBs + b_byte + (uint32_t)(nj * 16 * ROWF * 4 + ks * 32));
#pragma unroll
            for (int mi = 0; mi < 2; mi++)
#pragma unroll
                for (int nj = 0; nj < 4; nj++) {
                    mma_tf32(acc[mi][nj * 2 + 0], afr[mi], bfr[nj][0], bfr[nj][1]);
                    mma_tf32(acc[mi][nj * 2 + 1], afr[mi], bfr[nj][2], bfr[nj][3]);
                }
        }

        stage++;
        if (stage == NSTAGE) stage = 0;
    }

    // ---- epilogue: scale by rsigma, write NCHW ----
    const int gid = lane >> 2;
    const int tig = lane & 3;
    const int ncol0 = (n0c & 4095) + wn + tig * 2;
#pragma unroll
    for (int mi = 0; mi < 2; mi++) {
#pragma unroll
        for (int half = 0; half < 2; half++) {
            int co = m0c + wm + mi * 16 + gid + half * 8;
            float rs = g_rsigma[b * COUT + co];
            float* orow = out + (size_t)(b * COUT + co) * 4096 + ncol0;
#pragma unroll
            for (int nj8 = 0; nj8 < 8; nj8++) {
                float2 v;
                v.x = acc[mi][nj8][half * 2 + 0] * rs;
                v.y = acc[mi][nj8][half * 2 + 1] * rs;
                *(float2*)(orow + nj8 * 8) = v;
            }
        }
    }
}

// ---------------------------------------------------------------------------
extern "C" void kernel_launch(void* const* d_in, const int* in_sizes, int n_in,
                              void* d_out, int out_size) {
    const float* x     = (const float*)d_in[0];  // [8,256,64,64]
    const float* style = (const float*)d_in[1];  // [8,256]
    const float* w     = (const float*)d_in[2];  // [256,256,3,3]
    float* out = (float*)d_out;

    wsq_kernel<<<(COUT * CIN + 255) / 256, 256>>>(w);
    sigma_kernel<<<BSZ, 256>>>(style);
    wt_kernel<<<(COUT * KK + 255) / 256, 256>>>(w);
    {
        int n4 = BSZ * CIN * HH * WW / 4;
        modx_kernel<<<(n4 + 255) / 256, 256>>>(x, style);
    }

    const int dyn = NSTAGE * STG_B;  // 122880 B
    cudaFuncSetAttribute(conv_mma, cudaFuncAttributeMaxDynamicSharedMemorySize, dyn);
    dim3 grid(NTOT / BN, COUT / BM);  // (128, 2)
    conv_mma<<<grid, THREADS, dyn>>>(out);
}

// round 7
// speedup vs baseline: 1.5961x; 1.5961x over previous
#include <cuda_runtime.h>
#include <cstdint>

#define BSZ 8
#define CIN 256
#define COUT 256
#define HH 64
#define WW 64
#define KK (CIN * 9)          // 2304
#define NTOT (BSZ * HH * WW)  // 32768

#define BM 128
#define BN 256
#define BK 16
#define NITER (KK / BK)       // 144
#define THREADS 512

// Scratch
__device__ float g_xm[BSZ * CIN * HH * WW];   // style-modulated, tf32-rounded input
__device__ float g_wt[COUT * KK];             // tap-major tf32 weights: [co][tap][ci]
__device__ float g_wsq[COUT * CIN];
__device__ float g_rsigma[BSZ * COUT];

// ---------------------------------------------------------------------------
__device__ __forceinline__ uint32_t smem_u32(const void* p) {
    uint32_t a;
    asm("{ .reg .u64 t; cvta.to.shared.u64 t, %1; cvt.u32.u64 %0, t; }" : "=r"(a) : "l"(p));
    return a;
}
__device__ __forceinline__ float to_tf32(float f) {
    uint32_t u;
    asm("cvt.rna.tf32.f32 %0, %1;" : "=r"(u) : "f"(f));
    return __uint_as_float(u);
}
__device__ __forceinline__ void ldsm_x4(uint32_t* r, uint32_t addr) {
    asm volatile("ldmatrix.sync.aligned.m8n8.x4.shared.b16 {%0,%1,%2,%3}, [%4];"
                 : "=r"(r[0]), "=r"(r[1]), "=r"(r[2]), "=r"(r[3]) : "r"(addr));
}
__device__ __forceinline__ void mma_tf32(float* d, const uint32_t* a, uint32_t b0, uint32_t b1) {
    asm volatile(
        "mma.sync.aligned.m16n8k8.row.col.f32.tf32.tf32.f32 "
        "{%0,%1,%2,%3}, {%4,%5,%6,%7}, {%8,%9}, {%0,%1,%2,%3};"
        : "+f"(d[0]), "+f"(d[1]), "+f"(d[2]), "+f"(d[3])
        : "r"(a[0]), "r"(a[1]), "r"(a[2]), "r"(a[3]), "r"(b0), "r"(b1));
}

// ---------------------------------------------------------------------------
// Pre-kernels
// ---------------------------------------------------------------------------
__global__ void wsq_kernel(const float* __restrict__ w) {
    int idx = blockIdx.x * blockDim.x + threadIdx.x;
    if (idx >= COUT * CIN) return;
    const float* p = w + idx * 9;
    float s = 0.f;
#pragma unroll
    for (int i = 0; i < 9; i++) s += p[i] * p[i];
    g_wsq[idx] = s;
}

__global__ void sigma_kernel(const float* __restrict__ style) {
    __shared__ float s2[CIN];
    int b = blockIdx.x;
    for (int i = threadIdx.x; i < CIN; i += blockDim.x) {
        float s = style[b * CIN + i];
        s2[i] = s * s;
    }
    __syncthreads();
    int co = threadIdx.x;
    const float* wr = g_wsq + co * CIN;
    float acc = 0.f;
#pragma unroll 4
    for (int ci = 0; ci < CIN; ci++) acc += s2[ci] * wr[ci];
    g_rsigma[b * COUT + co] = rsqrtf(acc + 1e-8f);
}

// tap-major transpose + tf32 round: g_wt[co][tap*256+ci] = rna(w[co][ci*9+tap])
__global__ void wt_kernel(const float* __restrict__ w) {
    int idx = blockIdx.x * blockDim.x + threadIdx.x;
    if (idx >= COUT * KK) return;
    int co = idx / KK;
    int r = idx - co * KK;
    int tap = r >> 8;
    int ci = r & 255;
    g_wt[idx] = to_tf32(w[co * KK + ci * 9 + tap]);
}

__global__ void modx_kernel(const float* __restrict__ x, const float* __restrict__ style) {
    int idx = blockIdx.x * blockDim.x + threadIdx.x;
    const int n4 = BSZ * CIN * HH * WW / 4;
    if (idx >= n4) return;
    int plane = idx / (HH * WW / 4);
    float s = style[plane];
    float4 v = ((const float4*)x)[idx];
    v.x = to_tf32(v.x * s);
    v.y = to_tf32(v.y * s);
    v.z = to_tf32(v.z * s);
    v.w = to_tf32(v.w * s);
    ((float4*)g_xm)[idx] = v;
}

// ---------------------------------------------------------------------------
// tf32 mma.sync implicit-GEMM conv. R4 envelope (512 thr, 16 warps of 32x64,
// 2-stage reg-staged double buffer) + tap-major K + ONE barrier per iter.
// ---------------------------------------------------------------------------
#define ROWF 20                       // floats per smem row (16 + 4 pad)
#define SA_F (BM * ROWF)              // 2560 floats
#define SB_F (BN * ROWF)              // 5120 floats
#define STG_F (SA_F + SB_F)           // 7680 floats = 30720 B

__global__ __launch_bounds__(THREADS, 1)
void conv_mma(float* __restrict__ out) {
    extern __shared__ float sm[];
    const uint32_t smb = smem_u32(sm);

    const int tid = threadIdx.x;
    const int lane = tid & 31;
    const int warp = tid >> 5;

    const int m0c = blockIdx.y * BM;
    const int n0c = blockIdx.x * BN;
    const int b = n0c >> 12;
    const float* xb = g_xm + (size_t)b * CIN * 4096;

    // --- A loader: row-major tap-major weights, contiguous float4 ---
    const int arow = tid >> 2;
    const int aq   = (tid & 3) * 4;
    const float* wa_base = g_wt + (size_t)(m0c + arow) * KK + aq;
    const uint32_t a_sts = (uint32_t)((arow * ROWF + aq) * 4);

    // --- B loader: 2 threads/row, 8 consecutive ci-planes each ---
    const int bn = tid >> 1;
    const int bh = (tid & 1) * 8;
    const int nn = n0c + bn;
    const int wc = nn & 63;
    const int hr = (nn >> 6) & 63;
    const uint32_t b_sts = (uint32_t)((SA_F + bn * ROWF + bh) * 4);

    // --- compute mapping (verified R4) ---
    const int wm = (warp >> 2) * 32;
    const int wn = (warp & 3) * 64;
    const uint32_t a_byte = (uint32_t)(((wm + (lane & 15)) * ROWF + (lane >> 4) * 4) * 4);
    const uint32_t b_byte =
        (uint32_t)(((wn + (lane & 7) + ((lane >> 4) << 3)) * ROWF + ((lane >> 3) & 1) * 4) * 4);

    float acc[2][8][4];
#pragma unroll
    for (int i = 0; i < 2; i++)
#pragma unroll
        for (int j = 0; j < 8; j++)
#pragma unroll
            for (int q = 0; q < 4; q++) acc[i][j][q] = 0.f;

    uint32_t areg[4];
    float breg[8];

    // --- tap state: constants for current load tap, advanced every 16 iters ---
    int kh = 0, kw = 0;
    bool valid = (hr > 0) && (wc > 0);              // tap (0,0): hs=hr-1, ws=wc-1
    const float* bsrc = xb + ((hr - 1) * 64 + (wc - 1)) + (size_t)bh * 4096;

    auto advance_tap = [&]() {
        kw++;
        if (kw == 3) { kw = 0; kh++; }
        int hs = hr + kh - 1;
        int ws = wc + kw - 1;
        valid = ((unsigned)hs < 64u) && ((unsigned)ws < 64u);
        bsrc = xb + (hs * 64 + ws) + (size_t)bh * 4096;
    };

    auto ldg_tile = [&](int lt) {
        // A: float4 of tap-major weights
        float4 av = *(const float4*)(wa_base + lt * BK);
        areg[0] = __float_as_uint(to_tf32(av.x));
        areg[1] = __float_as_uint(to_tf32(av.y));
        areg[2] = __float_as_uint(to_tf32(av.z));
        areg[3] = __float_as_uint(to_tf32(av.w));
        // B: 8 planes, stride 4096 floats; ci0 = (lt & 15) * 16
        const float* p = bsrc + (size_t)((lt & 15) << 4) * 4096;
#pragma unroll
        for (int j = 0; j < 8; j++)
            breg[j] = valid ? p[(size_t)j * 4096] : 0.f;
    };
    auto sts_tile = [&](int s) {
        uint32_t sAa = smb + (uint32_t)(s * STG_F * 4) + a_sts;
        asm volatile("st.shared.v4.b32 [%0], {%1,%2,%3,%4};"
                     :: "r"(sAa), "r"(areg[0]), "r"(areg[1]), "r"(areg[2]), "r"(areg[3]) : "memory");
        uint32_t sBa = smb + (uint32_t)(s * STG_F * 4) + b_sts;
        asm volatile("st.shared.v4.b32 [%0], {%1,%2,%3,%4};"
                     :: "r"(sBa),
                        "r"(__float_as_uint(breg[0])), "r"(__float_as_uint(breg[1])),
                        "r"(__float_as_uint(breg[2])), "r"(__float_as_uint(breg[3])) : "memory");
        asm volatile("st.shared.v4.b32 [%0], {%1,%2,%3,%4};"
                     :: "r"(sBa + 16u),
                        "r"(__float_as_uint(breg[4])), "r"(__float_as_uint(breg[5])),
                        "r"(__float_as_uint(breg[6])), "r"(__float_as_uint(breg[7])) : "memory");
    };

    // ---- prologue: load+store tile 0 (tap 0) ----
    ldg_tile(0);
    sts_tile(0);
    __syncthreads();

    for (int it = 0; it < NITER; it++) {
        const int s = it & 1;
        const int lt = it + 1;
        if (lt < NITER) {
            if ((lt & 15) == 0) advance_tap();
            ldg_tile(lt);          // LDG latency hidden under compute
        }

        // ---- compute on stage s ----
        const uint32_t sAs = smb + (uint32_t)(s * STG_F * 4);
        const uint32_t sBs = sAs + (uint32_t)(SA_F * 4);
#pragma unroll
        for (int ks = 0; ks < 2; ks++) {
            uint32_t afr[2][4], bfr[4][4];
#pragma unroll
            for (int mi = 0; mi < 2; mi++)
                ldsm_x4(afr[mi], sAs + a_byte + (uint32_t)(mi * 16 * ROWF * 4 + ks * 32));
#pragma unroll
            for (int nj = 0; nj < 4; nj++)
                ldsm_x4(bfr[nj], sBs + b_byte + (uint32_t)(nj * 16 * ROWF * 4 + ks * 32));
#pragma unroll
            for (int mi = 0; mi < 2; mi++)
#pragma unroll
                for (int nj = 0; nj < 4; nj++) {
                    mma_tf32(acc[mi][nj * 2 + 0], afr[mi], bfr[nj][0], bfr[nj][1]);
                    mma_tf32(acc[mi][nj * 2 + 1], afr[mi], bfr[nj][2], bfr[nj][3]);
                }
        }

        // ---- store next tile into the other stage; single barrier ----
        if (lt < NITER) sts_tile(s ^ 1);
        __syncthreads();
    }

    // ---- epilogue: scale by rsigma, write NCHW ----
    const int gid = lane >> 2;
    const int tig = lane & 3;
    const int ncol0 = (n0c & 4095) + wn + tig * 2;
#pragma unroll
    for (int mi = 0; mi < 2; mi++) {
#pragma unroll
        for (int half = 0; half < 2; half++) {
            int co = m0c + wm + mi * 16 + gid + half * 8;
            float rs = g_rsigma[b * COUT + co];
            float* orow = out + (size_t)(b * COUT + co) * 4096 + ncol0;
#pragma unroll
            for (int nj8 = 0; nj8 < 8; nj8++) {
                float2 v;
                v.x = acc[mi][nj8][half * 2 + 0] * rs;
                v.y = acc[mi][nj8][half * 2 + 1] * rs;
                *(float2*)(orow + nj8 * 8) = v;
            }
        }
    }
}

// ---------------------------------------------------------------------------
extern "C" void kernel_launch(void* const* d_in, const int* in_sizes, int n_in,
                              void* d_out, int out_size) {
    const float* x     = (const float*)d_in[0];  // [8,256,64,64]
    const float* style = (const float*)d_in[1];  // [8,256]
    const float* w     = (const float*)d_in[2];  // [256,256,3,3]
    float* out = (float*)d_out;

    wsq_kernel<<<(COUT * CIN + 255) / 256, 256>>>(w);
    sigma_kernel<<<BSZ, 256>>>(style);
    wt_kernel<<<(COUT * KK + 255) / 256, 256>>>(w);
    {
        int n4 = BSZ * CIN * HH * WW / 4;
        modx_kernel<<<(n4 + 255) / 256, 256>>>(x, style);
    }

    const int dyn = 2 * STG_F * 4;  // 61440 B
    cudaFuncSetAttribute(conv_mma, cudaFuncAttributeMaxDynamicSharedMemorySize, dyn);
    dim3 grid(NTOT / BN, COUT / BM);  // (128, 2)
    conv_mma<<<grid, THREADS, dyn>>>(out);
}